// round 3
// baseline (speedup 1.0000x reference)
#include <cuda_runtime.h>
#include <cuda_bf16.h>
#include <math.h>

// Problem constants
#define BATCH 4
#define SEQ   2048
#define DM    1024
#define NH    16
#define DK    64
#define MROWS (BATCH * SEQ)      // 8192

// ---------------- scratch (device globals; no runtime alloc) ----------------
__device__ float g_q[MROWS * DM];
__device__ float g_k[MROWS * DM];
__device__ float g_v[MROWS * DM];
__device__ float g_kt[MROWS * DM];   // K transposed: [B][H][DK][SEQ]
__device__ float g_attn[MROWS * DM];

// ---------------- SGEMM with bias: C[M,N] = A[M,K] @ W[K,N] + b --------------
#define PM 128
#define PN 128
#define PKD 8

__global__ __launch_bounds__(256) void gemm_bias_kernel(
    const float* __restrict__ A, const float* __restrict__ W,
    const float* __restrict__ bias, float* __restrict__ C,
    int M, int N, int K)
{
    __shared__ float As[PKD][PM];
    __shared__ float Bs[PKD][PN];

    const int tid = threadIdx.x;
    const int bm = blockIdx.y * PM;
    const int bn = blockIdx.x * PN;

    const int arow  = tid >> 1;
    const int acol4 = (tid & 1) * 4;
    const int brow  = tid >> 5;
    const int bcol4 = (tid & 31) * 4;

    const int tx = tid & 15;
    const int ty = tid >> 4;

    float acc[8][8];
    #pragma unroll
    for (int i = 0; i < 8; i++)
        #pragma unroll
        for (int j = 0; j < 8; j++) acc[i][j] = 0.f;

    for (int k0 = 0; k0 < K; k0 += PKD) {
        float4 a4 = *(const float4*)&A[(size_t)(bm + arow) * K + k0 + acol4];
        As[acol4 + 0][arow] = a4.x;
        As[acol4 + 1][arow] = a4.y;
        As[acol4 + 2][arow] = a4.z;
        As[acol4 + 3][arow] = a4.w;
        *(float4*)&Bs[brow][bcol4] =
            *(const float4*)&W[(size_t)(k0 + brow) * N + bn + bcol4];
        __syncthreads();

        #pragma unroll
        for (int k = 0; k < PKD; k++) {
            float4 ra0 = *(const float4*)&As[k][ty * 8];
            float4 ra1 = *(const float4*)&As[k][ty * 8 + 4];
            float4 rb0 = *(const float4*)&Bs[k][tx * 8];
            float4 rb1 = *(const float4*)&Bs[k][tx * 8 + 4];
            float ra[8] = {ra0.x, ra0.y, ra0.z, ra0.w, ra1.x, ra1.y, ra1.z, ra1.w};
            float rb[8] = {rb0.x, rb0.y, rb0.z, rb0.w, rb1.x, rb1.y, rb1.z, rb1.w};
            #pragma unroll
            for (int i = 0; i < 8; i++)
                #pragma unroll
                for (int j = 0; j < 8; j++)
                    acc[i][j] += ra[i] * rb[j];
        }
        __syncthreads();
    }

    #pragma unroll
    for (int i = 0; i < 8; i++) {
        const int row = bm + ty * 8 + i;
        #pragma unroll
        for (int j = 0; j < 8; j += 4) {
            const int col = bn + tx * 8 + j;
            float4 o;
            o.x = acc[i][j + 0] + bias[col + 0];
            o.y = acc[i][j + 1] + bias[col + 1];
            o.z = acc[i][j + 2] + bias[col + 2];
            o.w = acc[i][j + 3] + bias[col + 3];
            *(float4*)&C[(size_t)row * N + col] = o;
        }
    }
}

// ---------------- K transpose: [B,S,H,DK] -> [B,H,DK,S] ---------------------
__global__ __launch_bounds__(256) void transpose_k_kernel(
    const float* __restrict__ in, float* __restrict__ out)
{
    __shared__ float t[32][33];
    const int bh = blockIdx.z;
    const int b  = bh >> 4;
    const int h  = bh & 15;
    const int s0 = blockIdx.x * 32;
    const int d0 = blockIdx.y * 32;
    const int txv = threadIdx.x;   // 0..31
    const int tyv = threadIdx.y;   // 0..7

    const float* src = in + (size_t)b * SEQ * DM + (size_t)h * DK;
    #pragma unroll
    for (int k = 0; k < 32; k += 8)
        t[tyv + k][txv] = src[(size_t)(s0 + tyv + k) * DM + d0 + txv];
    __syncthreads();

    float* dst = out + ((size_t)bh * DK + d0) * SEQ + s0;
    #pragma unroll
    for (int k = 0; k < 32; k += 8)
        dst[(size_t)(tyv + k) * SEQ + txv] = t[txv][tyv + k];
}

// ---------------- Flash attention (fp32, 128x128 tile, 8x8 micro) -----------
#define BQ  128
#define BKV 128
// smem floats: Qt 64x128, Kts 64x128, Vs 128x64, Pt 128x128 (swizzled), m/l/f 3x128
#define ATTN_SMEM ((64*128*3 + 128*128 + 3*128) * sizeof(float))

__global__ __launch_bounds__(256) void attn_kernel(
    const float* __restrict__ gq, const float* __restrict__ gkt,
    const float* __restrict__ gv, float* __restrict__ gout)
{
    extern __shared__ float sm[];
    float* Qt  = sm;                    // [DK][BQ]   Qt[d][r]
    float* Kts = Qt  + 64 * 128;        // [DK][BKV]  Kts[d][j]
    float* Vs  = Kts + 64 * 128;        // [BKV][DK]  Vs[j][d]
    float* Pt  = Vs  + 64 * 128;        // [BKV][BQ]  swizzled Pt[j][r]
    float* smM = Pt  + 128 * 128;       // [BQ] running max
    float* smL = smM + 128;             // [BQ] running denom
    float* smF = smL + 128;             // [BQ] rescale factor this iter

    const int tid = threadIdx.x;
    const int tx  = tid & 15;           // scores: j-cols group
    const int ty  = tid >> 4;           // scores: r-rows group
    const int txp = tid & 7;            // PV: d-cols group
    const int typ = tid >> 3;           // PV: r-rows group (0..31)
    const int q0  = blockIdx.x * BQ;
    const int b   = blockIdx.y >> 4;
    const int h   = blockIdx.y & 15;

    const float* qbase = gq  + (size_t)b * SEQ * DM + (size_t)h * DK;
    const float* ktb   = gkt + (size_t)blockIdx.y * DK * SEQ;   // rows d, cols s
    const float* vbase = gv  + (size_t)b * SEQ * DM + (size_t)h * DK;

    // Load Q tile transposed: Qt[d][r] (once per block; scatter cost amortized)
    for (int i = tid; i < BQ * DK / 4; i += 256) {
        int r  = i >> 4;                // 0..127
        int c4 = (i & 15) * 4;          // 0..60
        float4 v = *(const float4*)&qbase[(size_t)(q0 + r) * DM + c4];
        Qt[(c4 + 0) * BQ + r] = v.x;
        Qt[(c4 + 1) * BQ + r] = v.y;
        Qt[(c4 + 2) * BQ + r] = v.z;
        Qt[(c4 + 3) * BQ + r] = v.w;
    }
    if (tid < 128) { smM[tid] = -1e30f; smL[tid] = 0.f; }

    float accO[4][8];
    #pragma unroll
    for (int i = 0; i < 4; i++)
        #pragma unroll
        for (int p = 0; p < 8; p++) accO[i][p] = 0.f;

    const float scale = 0.125f;         // 1/sqrt(64)

    for (int kt = 0; kt < SEQ / BKV; kt++) {
        const int j0 = kt * BKV;
        __syncthreads();   // previous PV reads of Kts/Vs/Pt done

        // Copy K^T tile rows (coalesced, conflict-free)
        for (int i = tid; i < 64 * BKV / 4; i += 256) {
            int d  = i >> 5;            // 32 float4 per row
            int c4 = (i & 31) * 4;
            *(float4*)&Kts[d * BKV + c4] =
                *(const float4*)&ktb[(size_t)d * SEQ + j0 + c4];
        }
        // Copy V tile (natural)
        for (int i = tid; i < BKV * DK / 4; i += 256) {
            int r  = i >> 4;            // 16 float4 per row
            int c4 = (i & 15) * 4;
            *(float4*)&Vs[r * DK + c4] =
                *(const float4*)&vbase[(size_t)(j0 + r) * DM + c4];
        }
        __syncthreads();

        // ---- scores: s[i][p] = Q[r][:] . K[j][:],  r=ty*8+i, j=tx*8+p ----
        float s[8][8];
        #pragma unroll
        for (int i = 0; i < 8; i++)
            #pragma unroll
            for (int p = 0; p < 8; p++) s[i][p] = 0.f;

        #pragma unroll 2
        for (int d = 0; d < DK; d++) {
            float4 a0 = *(const float4*)&Qt[d * BQ + ty * 8];
            float4 a1 = *(const float4*)&Qt[d * BQ + ty * 8 + 4];
            float4 b0 = *(const float4*)&Kts[d * BKV + tx * 8];
            float4 b1 = *(const float4*)&Kts[d * BKV + tx * 8 + 4];
            float ra[8] = {a0.x, a0.y, a0.z, a0.w, a1.x, a1.y, a1.z, a1.w};
            float rb[8] = {b0.x, b0.y, b0.z, b0.w, b1.x, b1.y, b1.z, b1.w};
            #pragma unroll
            for (int i = 0; i < 8; i++)
                #pragma unroll
                for (int p = 0; p < 8; p++)
                    s[i][p] += ra[i] * rb[p];
        }

        // ---- online softmax (row state in smem; rows owned by tx-groups) ----
        #pragma unroll
        for (int i = 0; i < 8; i++) {
            const int r = ty * 8 + i;
            #pragma unroll
            for (int p = 0; p < 8; p++) s[i][p] *= scale;

            float rmax = s[i][0];
            #pragma unroll
            for (int p = 1; p < 8; p++) rmax = fmaxf(rmax, s[i][p]);
            #pragma unroll
            for (int off = 8; off > 0; off >>= 1)
                rmax = fmaxf(rmax, __shfl_xor_sync(0xffffffffu, rmax, off));

            const float mold = smM[r];
            const float mnew = fmaxf(mold, rmax);

            float rs = 0.f;
            #pragma unroll
            for (int p = 0; p < 8; p++) {
                s[i][p] = __expf(s[i][p] - mnew);
                rs += s[i][p];
            }
            #pragma unroll
            for (int off = 8; off > 0; off >>= 1)
                rs += __shfl_xor_sync(0xffffffffu, rs, off);

            if (tx == 0) {
                const float f = __expf(mold - mnew);
                smM[r] = mnew;
                smF[r] = f;
                smL[r] = smL[r] * f + rs;
            }

            // store P transposed + swizzled: chunk c=(r>>2), c' = c ^ ((j>>3)&7)
            const int jsw = tx & 7;     // (j>>3)&7 for j = tx*8+p
            // i handled via two float4 quads below (after all i computed)
        }

        // Pt stores: for each p, two float4 column-quads (i in {0..3},{4..7})
        #pragma unroll
        for (int p = 0; p < 8; p++) {
            const int j = tx * 8 + p;
            const int jsw = tx & 7;
            #pragma unroll
            for (int iq = 0; iq < 2; iq++) {
                const int c  = 2 * ty + iq;        // (r>>2) for r = ty*8+iq*4
                const int cs = c ^ jsw;
                float4 v = make_float4(s[iq*4+0][p], s[iq*4+1][p],
                                       s[iq*4+2][p], s[iq*4+3][p]);
                *(float4*)&Pt[j * BQ + cs * 4] = v;
            }
        }
        __syncthreads();   // Pt + smF visible

        // ---- PV: accO[i][p] for O[typ*4+i][txp*8+p] ----
        float fr[4];
        #pragma unroll
        for (int i = 0; i < 4; i++) fr[i] = smF[typ * 4 + i];
        #pragma unroll
        for (int i = 0; i < 4; i++)
            #pragma unroll
            for (int p = 0; p < 8; p++) accO[i][p] *= fr[i];

        #pragma unroll 2
        for (int j = 0; j < BKV; j++) {
            const int cs = typ ^ ((j >> 3) & 7);   // chunk typ = (typ*4)>>2
            float4 rp4 = *(const float4*)&Pt[j * BQ + cs * 4];
            float4 v0  = *(const float4*)&Vs[j * DK + txp * 8];
            float4 v1  = *(const float4*)&Vs[j * DK + txp * 8 + 4];
            float rp[4] = {rp4.x, rp4.y, rp4.z, rp4.w};
            float rv[8] = {v0.x, v0.y, v0.z, v0.w, v1.x, v1.y, v1.z, v1.w};
            #pragma unroll
            for (int i = 0; i < 4; i++)
                #pragma unroll
                for (int p = 0; p < 8; p++)
                    accO[i][p] += rp[i] * rv[p];
        }
    }

    // ---- epilogue: normalize, write O ----
    float* obase = gout + (size_t)b * SEQ * DM + (size_t)h * DK;
    #pragma unroll
    for (int i = 0; i < 4; i++) {
        const int r = typ * 4 + i;
        const float inv = 1.f / smL[r];
        float4 o0, o1;
        o0.x = accO[i][0] * inv; o0.y = accO[i][1] * inv;
        o0.z = accO[i][2] * inv; o0.w = accO[i][3] * inv;
        o1.x = accO[i][4] * inv; o1.y = accO[i][5] * inv;
        o1.z = accO[i][6] * inv; o1.w = accO[i][7] * inv;
        *(float4*)&obase[(size_t)(q0 + r) * DM + txp * 8]     = o0;
        *(float4*)&obase[(size_t)(q0 + r) * DM + txp * 8 + 4] = o1;
    }
}

// ---------------- launch -----------------------------------------------------
extern "C" void kernel_launch(void* const* d_in, const int* in_sizes, int n_in,
                              void* d_out, int out_size)
{
    const float* Q  = (const float*)d_in[0];
    const float* K  = (const float*)d_in[1];
    const float* V  = (const float*)d_in[2];
    const float* Wq = (const float*)d_in[3];
    const float* bq = (const float*)d_in[4];
    const float* Wk = (const float*)d_in[5];
    const float* bk = (const float*)d_in[6];
    const float* Wv = (const float*)d_in[7];
    const float* bv = (const float*)d_in[8];
    const float* Wo = (const float*)d_in[9];
    const float* bo = (const float*)d_in[10];
    float* out = (float*)d_out;

    void *pq, *pk, *pv, *pkt, *pa;
    cudaGetSymbolAddress(&pq,  g_q);
    cudaGetSymbolAddress(&pk,  g_k);
    cudaGetSymbolAddress(&pv,  g_v);
    cudaGetSymbolAddress(&pkt, g_kt);
    cudaGetSymbolAddress(&pa,  g_attn);

    static bool attr_set = false;
    if (!attr_set) {
        cudaFuncSetAttribute(attn_kernel,
                             cudaFuncAttributeMaxDynamicSharedMemorySize,
                             (int)ATTN_SMEM);
        attr_set = true;
    }

    dim3 pgrid(DM / PN, MROWS / PM);   // (8, 64)
    dim3 pblock(256);

    gemm_bias_kernel<<<pgrid, pblock>>>(Q, Wq, bq, (float*)pq, MROWS, DM, DM);
    gemm_bias_kernel<<<pgrid, pblock>>>(K, Wk, bk, (float*)pk, MROWS, DM, DM);
    gemm_bias_kernel<<<pgrid, pblock>>>(V, Wv, bv, (float*)pv, MROWS, DM, DM);

    dim3 tgrid(SEQ / 32, DK / 32, BATCH * NH);   // (64, 2, 64)
    transpose_k_kernel<<<tgrid, dim3(32, 8)>>>((const float*)pk, (float*)pkt);

    dim3 agrid(SEQ / BQ, BATCH * NH);  // (16, 64)
    attn_kernel<<<agrid, 256, ATTN_SMEM>>>((const float*)pq, (const float*)pkt,
                                           (const float*)pv, (float*)pa);

    gemm_bias_kernel<<<pgrid, pblock>>>((const float*)pa, Wo, bo, out, MROWS, DM, DM);
}

// round 4
// speedup vs baseline: 3.5953x; 3.5953x over previous
#include <cuda_runtime.h>
#include <cuda_bf16.h>
#include <math.h>
#include <stdint.h>

// Problem constants
#define BATCH 4
#define SEQ   2048
#define DM    1024
#define NH    16
#define DK    64
#define MROWS (BATCH * SEQ)      // 8192

// ---------------- scratch (device globals; no runtime alloc) ----------------
__device__ float g_q[MROWS * DM];
__device__ float g_k[MROWS * DM];
__device__ float g_v[MROWS * DM];
__device__ float g_attn[MROWS * DM];

// ---------------- helpers ----------------------------------------------------
__device__ __forceinline__ float to_tf32(float x) {
    uint32_t u;
    asm("cvt.rna.tf32.f32 %0, %1;" : "=r"(u) : "f"(x));
    return __uint_as_float(u);
}
__device__ __forceinline__ float fast_exp2(float x) {
    float y;
    asm("ex2.approx.f32 %0, %1;" : "=f"(y) : "f"(x));
    return y;
}
// D = A(16x8 tf32, row) * B(8x8 tf32, col) + C   (in-place C allowed)
__device__ __forceinline__ void mma_tf32(float* d, const uint32_t* a,
                                         const uint32_t* b, const float* c) {
    asm volatile(
        "mma.sync.aligned.m16n8k8.row.col.f32.tf32.tf32.f32 "
        "{%0,%1,%2,%3}, {%4,%5,%6,%7}, {%8,%9}, {%10,%11,%12,%13};\n"
        : "=f"(d[0]), "=f"(d[1]), "=f"(d[2]), "=f"(d[3])
        : "r"(a[0]), "r"(a[1]), "r"(a[2]), "r"(a[3]),
          "r"(b[0]), "r"(b[1]),
          "f"(c[0]), "f"(c[1]), "f"(c[2]), "f"(c[3]));
}

// ---------------- tf32 GEMM with bias: C = A[M,K] @ W[K,N] + b ---------------
// 128x128x32 tile, 256 threads (8 warps, 2x4), warp tile 64x32.
#define APAD 36
#define BPAD 136

__global__ __launch_bounds__(256) void gemm_bias_tf32(
    const float* __restrict__ A, const float* __restrict__ W,
    const float* __restrict__ bias, float* __restrict__ C,
    int M, int N, int K)
{
    __shared__ float As[128 * APAD];   // [m][k] pad 36
    __shared__ float Bs[32 * BPAD];    // [k][n] pad 136

    const int tid  = threadIdx.x;
    const int lane = tid & 31;
    const int warp = tid >> 5;
    const int g    = lane >> 2;
    const int tig  = lane & 3;
    const int wm   = warp >> 2;        // 0..1
    const int wn   = warp & 3;         // 0..3
    const int bm   = blockIdx.y * 128;
    const int bn   = blockIdx.x * 128;

    float acc[4][4][4];
    #pragma unroll
    for (int mi = 0; mi < 4; mi++)
        #pragma unroll
        for (int ni = 0; ni < 4; ni++)
            #pragma unroll
            for (int q = 0; q < 4; q++) acc[mi][ni][q] = 0.f;

    for (int k0 = 0; k0 < K; k0 += 32) {
        // A tile: 128 rows x 32 k  (1024 float4)
        #pragma unroll
        for (int it = 0; it < 4; it++) {
            int idx = tid + 256 * it;
            int r = idx >> 3, c4 = (idx & 7) * 4;
            float4 v = *(const float4*)&A[(size_t)(bm + r) * K + k0 + c4];
            float* p = &As[r * APAD + c4];
            p[0] = to_tf32(v.x); p[1] = to_tf32(v.y);
            p[2] = to_tf32(v.z); p[3] = to_tf32(v.w);
        }
        // B tile: 32 rows x 128 n
        #pragma unroll
        for (int it = 0; it < 4; it++) {
            int idx = tid + 256 * it;
            int r = idx >> 5, c4 = (idx & 31) * 4;
            float4 v = *(const float4*)&W[(size_t)(k0 + r) * N + bn + c4];
            float* p = &Bs[r * BPAD + c4];
            p[0] = to_tf32(v.x); p[1] = to_tf32(v.y);
            p[2] = to_tf32(v.z); p[3] = to_tf32(v.w);
        }
        __syncthreads();

        #pragma unroll
        for (int kk = 0; kk < 4; kk++) {
            uint32_t af[4][4];
            #pragma unroll
            for (int mi = 0; mi < 4; mi++) {
                const int m = wm * 64 + mi * 16;
                af[mi][0] = __float_as_uint(As[(m + g)     * APAD + kk * 8 + tig]);
                af[mi][1] = __float_as_uint(As[(m + g + 8) * APAD + kk * 8 + tig]);
                af[mi][2] = __float_as_uint(As[(m + g)     * APAD + kk * 8 + tig + 4]);
                af[mi][3] = __float_as_uint(As[(m + g + 8) * APAD + kk * 8 + tig + 4]);
            }
            #pragma unroll
            for (int ni = 0; ni < 4; ni++) {
                const int n = wn * 32 + ni * 8;
                uint32_t bf[2];
                bf[0] = __float_as_uint(Bs[(kk * 8 + tig)     * BPAD + n + g]);
                bf[1] = __float_as_uint(Bs[(kk * 8 + tig + 4) * BPAD + n + g]);
                #pragma unroll
                for (int mi = 0; mi < 4; mi++)
                    mma_tf32(acc[mi][ni], af[mi], bf, acc[mi][ni]);
            }
        }
        __syncthreads();
    }

    // epilogue: bias add, float2 stores
    #pragma unroll
    for (int mi = 0; mi < 4; mi++) {
        const int row = bm + wm * 64 + mi * 16 + g;
        #pragma unroll
        for (int ni = 0; ni < 4; ni++) {
            const int col = bn + wn * 32 + ni * 8 + 2 * tig;
            const float b0 = bias[col], b1 = bias[col + 1];
            float2 o0 = make_float2(acc[mi][ni][0] + b0, acc[mi][ni][1] + b1);
            float2 o1 = make_float2(acc[mi][ni][2] + b0, acc[mi][ni][3] + b1);
            *(float2*)&C[(size_t)row * N + col]       = o0;
            *(float2*)&C[(size_t)(row + 8) * N + col] = o1;
        }
    }
}

// ---------------- tf32 flash attention --------------------------------------
// Block: 128 threads (4 warps). BQ=64 q-rows (warp owns 16), BKV=64.
// smem: QP[64][76] (Q then P), Ks[64][76], Vs[64][72]
#define QPAD 76
#define VPAD 72
#define ATTN_SMEM ((64 * QPAD + 64 * QPAD + 64 * VPAD) * sizeof(float))

__global__ __launch_bounds__(128) void attn_tf32(
    const float* __restrict__ gq, const float* __restrict__ gk,
    const float* __restrict__ gv, float* __restrict__ gout)
{
    extern __shared__ float smf[];
    float* QP = smf;                   // [64][QPAD]  Q tile, reused for P
    float* Ks = QP + 64 * QPAD;        // [64][QPAD]
    float* Vs = Ks + 64 * QPAD;        // [64][VPAD]

    const int tid  = threadIdx.x;
    const int lane = tid & 31;
    const int warp = tid >> 5;         // 0..3
    const int g    = lane >> 2;
    const int tig  = lane & 3;
    const int q0   = blockIdx.x * 64;
    const int b    = blockIdx.y >> 4;
    const int h    = blockIdx.y & 15;

    const float* qb = gq + (size_t)b * SEQ * DM + (size_t)h * DK;
    const float* kb = gk + (size_t)b * SEQ * DM + (size_t)h * DK;
    const float* vb = gv + (size_t)b * SEQ * DM + (size_t)h * DK;

    // scale (1/sqrt(64)) * log2(e): softmax done in base-2
    const float qscale = 0.125f * 1.44269504f;

    // Load Q tile (scaled, tf32) : 64 rows x 16 float4
    for (int i = tid; i < 64 * 16; i += 128) {
        int r = i >> 4, c4 = (i & 15) * 4;
        float4 v = *(const float4*)&qb[(size_t)(q0 + r) * DM + c4];
        float* p = &QP[r * QPAD + c4];
        p[0] = to_tf32(v.x * qscale); p[1] = to_tf32(v.y * qscale);
        p[2] = to_tf32(v.z * qscale); p[3] = to_tf32(v.w * qscale);
    }
    __syncthreads();

    // Q fragments to registers (constant across all KV tiles)
    const int m = warp * 16;
    uint32_t qa[8][4];
    #pragma unroll
    for (int kk = 0; kk < 8; kk++) {
        qa[kk][0] = __float_as_uint(QP[(m + g)     * QPAD + kk * 8 + tig]);
        qa[kk][1] = __float_as_uint(QP[(m + g + 8) * QPAD + kk * 8 + tig]);
        qa[kk][2] = __float_as_uint(QP[(m + g)     * QPAD + kk * 8 + tig + 4]);
        qa[kk][3] = __float_as_uint(QP[(m + g + 8) * QPAD + kk * 8 + tig + 4]);
    }
    __syncthreads();   // all warps done reading Q before QP becomes P

    float oa[8][4];
    #pragma unroll
    for (int ni = 0; ni < 8; ni++)
        #pragma unroll
        for (int q = 0; q < 4; q++) oa[ni][q] = 0.f;
    float mr0 = -1e30f, mr1 = -1e30f, lr0 = 0.f, lr1 = 0.f;

    for (int kt = 0; kt < SEQ / 64; kt++) {
        const int j0 = kt * 64;
        __syncthreads();   // prior PV reads of Ks/Vs complete

        for (int i = tid; i < 64 * 16; i += 128) {
            int r = i >> 4, c4 = (i & 15) * 4;
            float4 kv = *(const float4*)&kb[(size_t)(j0 + r) * DM + c4];
            float4 vv = *(const float4*)&vb[(size_t)(j0 + r) * DM + c4];
            float* pk = &Ks[r * QPAD + c4];
            pk[0] = to_tf32(kv.x); pk[1] = to_tf32(kv.y);
            pk[2] = to_tf32(kv.z); pk[3] = to_tf32(kv.w);
            float* pv = &Vs[r * VPAD + c4];
            pv[0] = to_tf32(vv.x); pv[1] = to_tf32(vv.y);
            pv[2] = to_tf32(vv.z); pv[3] = to_tf32(vv.w);
        }
        __syncthreads();

        // ---- scores: S[r][j] = Q.K  (16 rows x 64 cols per warp) ----
        float sc[8][4];
        #pragma unroll
        for (int ni = 0; ni < 8; ni++)
            #pragma unroll
            for (int q = 0; q < 4; q++) sc[ni][q] = 0.f;

        #pragma unroll
        for (int kk = 0; kk < 8; kk++) {
            #pragma unroll
            for (int ni = 0; ni < 8; ni++) {
                uint32_t bf[2];
                bf[0] = __float_as_uint(Ks[(ni * 8 + g) * QPAD + kk * 8 + tig]);
                bf[1] = __float_as_uint(Ks[(ni * 8 + g) * QPAD + kk * 8 + tig + 4]);
                mma_tf32(sc[ni], qa[kk], bf, sc[ni]);
            }
        }

        // ---- online softmax (base 2) ----
        float rm0 = -1e30f, rm1 = -1e30f;
        #pragma unroll
        for (int ni = 0; ni < 8; ni++) {
            rm0 = fmaxf(rm0, fmaxf(sc[ni][0], sc[ni][1]));
            rm1 = fmaxf(rm1, fmaxf(sc[ni][2], sc[ni][3]));
        }
        rm0 = fmaxf(rm0, __shfl_xor_sync(0xffffffffu, rm0, 1));
        rm0 = fmaxf(rm0, __shfl_xor_sync(0xffffffffu, rm0, 2));
        rm1 = fmaxf(rm1, __shfl_xor_sync(0xffffffffu, rm1, 1));
        rm1 = fmaxf(rm1, __shfl_xor_sync(0xffffffffu, rm1, 2));

        const float mn0 = fmaxf(mr0, rm0);
        const float mn1 = fmaxf(mr1, rm1);
        const float f0 = fast_exp2(mr0 - mn0);
        const float f1 = fast_exp2(mr1 - mn1);
        mr0 = mn0; mr1 = mn1;

        float s0 = 0.f, s1 = 0.f;
        #pragma unroll
        for (int ni = 0; ni < 8; ni++) {
            sc[ni][0] = fast_exp2(sc[ni][0] - mn0);
            sc[ni][1] = fast_exp2(sc[ni][1] - mn0);
            sc[ni][2] = fast_exp2(sc[ni][2] - mn1);
            sc[ni][3] = fast_exp2(sc[ni][3] - mn1);
            s0 += sc[ni][0] + sc[ni][1];
            s1 += sc[ni][2] + sc[ni][3];
        }
        s0 += __shfl_xor_sync(0xffffffffu, s0, 1);
        s0 += __shfl_xor_sync(0xffffffffu, s0, 2);
        s1 += __shfl_xor_sync(0xffffffffu, s1, 1);
        s1 += __shfl_xor_sync(0xffffffffu, s1, 2);

        lr0 = lr0 * f0 + s0;
        lr1 = lr1 * f1 + s1;
        #pragma unroll
        for (int ni = 0; ni < 8; ni++) {
            oa[ni][0] *= f0; oa[ni][1] *= f0;
            oa[ni][2] *= f1; oa[ni][3] *= f1;
        }

        // ---- stage P (warp-private rows of QP) ----
        #pragma unroll
        for (int ni = 0; ni < 8; ni++) {
            const int col = ni * 8 + 2 * tig;
            *(float2*)&QP[(m + g) * QPAD + col] =
                make_float2(to_tf32(sc[ni][0]), to_tf32(sc[ni][1]));
            *(float2*)&QP[(m + g + 8) * QPAD + col] =
                make_float2(to_tf32(sc[ni][2]), to_tf32(sc[ni][3]));
        }
        __syncwarp();

        // ---- PV: O += P @ V ----
        #pragma unroll
        for (int kk = 0; kk < 8; kk++) {
            uint32_t pa[4];
            pa[0] = __float_as_uint(QP[(m + g)     * QPAD + kk * 8 + tig]);
            pa[1] = __float_as_uint(QP[(m + g + 8) * QPAD + kk * 8 + tig]);
            pa[2] = __float_as_uint(QP[(m + g)     * QPAD + kk * 8 + tig + 4]);
            pa[3] = __float_as_uint(QP[(m + g + 8) * QPAD + kk * 8 + tig + 4]);
            #pragma unroll
            for (int ni = 0; ni < 8; ni++) {
                uint32_t bf[2];
                bf[0] = __float_as_uint(Vs[(kk * 8 + tig)     * VPAD + ni * 8 + g]);
                bf[1] = __float_as_uint(Vs[(kk * 8 + tig + 4) * VPAD + ni * 8 + g]);
                mma_tf32(oa[ni], pa, bf, oa[ni]);
            }
        }
        __syncwarp();   // P reads done before next iteration overwrites
    }

    // ---- epilogue ----
    const float i0 = 1.f / lr0;
    const float i1 = 1.f / lr1;
    float* ob = gout + (size_t)b * SEQ * DM + (size_t)h * DK;
    const int row0 = q0 + m + g;
    #pragma unroll
    for (int ni = 0; ni < 8; ni++) {
        const int col = ni * 8 + 2 * tig;
        *(float2*)&ob[(size_t)row0 * DM + col] =
            make_float2(oa[ni][0] * i0, oa[ni][1] * i0);
        *(float2*)&ob[(size_t)(row0 + 8) * DM + col] =
            make_float2(oa[ni][2] * i1, oa[ni][3] * i1);
    }
}

// ---------------- launch -----------------------------------------------------
extern "C" void kernel_launch(void* const* d_in, const int* in_sizes, int n_in,
                              void* d_out, int out_size)
{
    const float* Q  = (const float*)d_in[0];
    const float* K  = (const float*)d_in[1];
    const float* V  = (const float*)d_in[2];
    const float* Wq = (const float*)d_in[3];
    const float* bq = (const float*)d_in[4];
    const float* Wk = (const float*)d_in[5];
    const float* bk = (const float*)d_in[6];
    const float* Wv = (const float*)d_in[7];
    const float* bv = (const float*)d_in[8];
    const float* Wo = (const float*)d_in[9];
    const float* bo = (const float*)d_in[10];
    float* out = (float*)d_out;

    void *pq, *pk, *pv, *pa;
    cudaGetSymbolAddress(&pq, g_q);
    cudaGetSymbolAddress(&pk, g_k);
    cudaGetSymbolAddress(&pv, g_v);
    cudaGetSymbolAddress(&pa, g_attn);

    static bool attr_set = false;
    if (!attr_set) {
        cudaFuncSetAttribute(attn_tf32,
                             cudaFuncAttributeMaxDynamicSharedMemorySize,
                             (int)ATTN_SMEM);
        attr_set = true;
    }

    dim3 pgrid(DM / 128, MROWS / 128);   // (8, 64)
    dim3 pblock(256);

    gemm_bias_tf32<<<pgrid, pblock>>>(Q, Wq, bq, (float*)pq, MROWS, DM, DM);
    gemm_bias_tf32<<<pgrid, pblock>>>(K, Wk, bk, (float*)pk, MROWS, DM, DM);
    gemm_bias_tf32<<<pgrid, pblock>>>(V, Wv, bv, (float*)pv, MROWS, DM, DM);

    dim3 agrid(SEQ / 64, BATCH * NH);    // (32, 64)
    attn_tf32<<<agrid, 128, ATTN_SMEM>>>((const float*)pq, (const float*)pk,
                                         (const float*)pv, (float*)pa);

    gemm_bias_tf32<<<pgrid, pblock>>>((const float*)pa, Wo, bo, out, MROWS, DM, DM);
}